// round 9
// baseline (speedup 1.0000x reference)
#include <cuda_runtime.h>
#include <cstdint>

// ---------------- problem / tiling constants ----------------
#define NN 8192
#define SS 3
#define DD 32
#define KSPLIT 8
#define KPER (NN / KSPLIT)            // 1024 K per item
#define BM 256
#define BK 32
#define SPI (KPER / BK)               // 32 stages per item
#define NMT (NN / BM)                 // 32 M-tiles
#define NITEMS (NMT * SS * KSPLIT)    // 768 work items
#define HALF_ITEMS (NITEMS / 2)       // 384 per gemm launch
#define NSTAGES 3

// smem layout (floats). Rows are exactly 32 floats (128B); XOR granule swizzle
// (g' = g ^ (row&7)) gives conflict-free STS phases and fragment LDS.
#define SA_FLOATS (BM * 32)                    // 8192
#define SB_FLOATS (DD * 32)                    // 1024
#define ABASE 0
#define BBASE (NSTAGES * SA_FLOATS)            // 24576
#define SMEM_FLOATS (BBASE + NSTAGES * SB_FLOATS)   // 27648 -> 110592 B

// ---------------- scratch (no cudaMalloc allowed) ----------------
__device__ float g_preT[SS * DD * NN];            // preT[s][o][n], tf32-rn, 3 MB
__device__ float g_part[SS * KSPLIT][NN * DD];    // K-split partials, 25 MB
__device__ int   g_ctr2[2];                       // work-steal counters (2 halves)

// tf32 round-to-nearest: +0x1000 into bit 12; MMA HW truncates low 13 bits.
__device__ __forceinline__ uint32_t tf32rn(uint32_t u) { return u + 0x1000u; }

// ---------------- cp.async helpers ----------------
__device__ __forceinline__ void cp16(uint32_t saddr, const float* g) {
    asm volatile("cp.async.cg.shared.global [%0], [%1], 16;"
                 :: "r"(saddr), "l"(g) : "memory");
}
__device__ __forceinline__ void cp_commit() {
    asm volatile("cp.async.commit_group;" ::: "memory");
}
__device__ __forceinline__ void cp_wait1() {
    asm volatile("cp.async.wait_group 1;" ::: "memory");
}

// ---------------------------------------------------------------------------
// Kernel 1: preT[s][o][n] = rn_tf32( b[s][o] + sum_i x[n][i]*W[s][i][o] )
// Also resets both work-steal counters each replay (determinism of launch).
// ---------------------------------------------------------------------------
__global__ __launch_bounds__(256) void pre_kernel(const float* __restrict__ x,
                                                  const float* __restrict__ W,
                                                  const float* __restrict__ b,
                                                  int nworkers) {
    if (blockIdx.x == 0 && blockIdx.y == 0 && blockIdx.z == 0 && threadIdx.x == 0) {
        g_ctr2[0] = nworkers;
        g_ctr2[1] = HALF_ITEMS + nworkers;
    }

    __shared__ float sx[32 * 33];
    __shared__ float sWs[32 * 8];
    __shared__ float sb8[8];

    int s = blockIdx.z, o0 = blockIdx.y * 8, n0 = blockIdx.x * 32;
    int t = threadIdx.x;

    for (int i = t; i < 32 * DD; i += 256) {
        int row = i >> 5, col = i & 31;
        sx[row * 33 + col] = x[(size_t)n0 * DD + i];
    }
    {
        int row = t >> 3, oc = t & 7;
        sWs[row * 8 + oc] = W[s * DD * DD + row * DD + o0 + oc];
    }
    if (t < 8) sb8[t] = b[s * DD + o0 + t];
    __syncthreads();

    int nl = t & 31, oj = t >> 5;
    float acc = sb8[oj];
#pragma unroll
    for (int i = 0; i < DD; i++)
        acc = fmaf(sx[nl * 33 + i], sWs[i * 8 + oj], acc);
    g_preT[(size_t)(s * DD + o0 + oj) * NN + n0 + nl] =
        __uint_as_float(tf32rn(__float_as_uint(acc)));
}

// ---------------------------------------------------------------------------
// Kernel 2: persistent work-stealing tf32 mma.sync GEMM over items [lo, hi).
// BM=256 (warp = m32 x n32), BK=32, 3-buffer cp.async pipeline (lead 2),
// XOR-swizzled smem, one barrier per stage, continuous across items.
// ---------------------------------------------------------------------------
__global__ void __launch_bounds__(256, 2) gemm_kernel(const float* __restrict__ adj,
                                                      int lo, int hi, int which) {
    extern __shared__ float smem[];
    __shared__ int s_next;
    const uint32_t sbase = (uint32_t)__cvta_generic_to_shared(smem);

    const int t = threadIdx.x;
    const int wid = t >> 5, lane = t & 31;
    const int r = lane >> 2, c = lane & 3;
    const int m0w = wid * 32;

    auto decode = [&](int it, const float*& aB, const float*& bB, int& s, int& z, int& mt) {
        mt = it & (NMT - 1);
        int sz = it >> 5;                 // NMT = 32
        s = sz % SS; z = sz / SS;
        aB = adj + ((size_t)(s * NN + mt * BM)) * NN + (size_t)z * KPER;
        bB = g_preT + (size_t)s * DD * NN + (size_t)z * KPER;
    };

    // issue stage st of item (aB,bB) into buffer `buf`
    auto issue = [&](const float* aB, const float* bB, int st, int buf) {
        uint32_t sa = sbase + (ABASE + buf * SA_FLOATS) * 4;
        uint32_t sb = sbase + (BBASE + buf * SB_FLOATS) * 4;
#pragma unroll
        for (int i = 0; i < 8; i++) {
            int idx = i * 256 + t;
            int row = idx >> 3, g = idx & 7;
            int gs = g ^ (row & 7);       // XOR swizzle
            cp16(sa + (row * 32 + gs * 4) * 4,
                 aB + (size_t)row * NN + st * BK + g * 4);
        }
        {
            int row = t >> 3, g = t & 7;
            int gs = g ^ (row & 7);
            cp16(sb + (row * 32 + gs * 4) * 4,
                 bB + (size_t)row * NN + st * BK + g * 4);
        }
    };

    // fragment smem index: row*32 + ((gran ^ r) << 2) + c, with gran = col>>2.
    auto compute = [&](int buf, float (&acc)[2][4][4]) {
        const uint32_t* sA = reinterpret_cast<const uint32_t*>(smem + ABASE + buf * SA_FLOATS);
        const uint32_t* sB = reinterpret_cast<const uint32_t*>(smem + BBASE + buf * SB_FLOATS);
#pragma unroll
        for (int k8 = 0; k8 < BK / 8; k8++) {
            int g0 = (k8 * 2) ^ r;        // swizzled granule for cols k0..k0+3
            int g1 = (k8 * 2 + 1) ^ r;    // cols k0+4..k0+7
            uint32_t a[2][4];
#pragma unroll
            for (int h = 0; h < 2; h++) { // h: m16 tile within warp (rows +0 / +16)
                int rb = m0w + h * 16 + r;
                a[h][0] = tf32rn(sA[rb * 32 + (g0 << 2) + c]);
                a[h][1] = tf32rn(sA[(rb + 8) * 32 + (g0 << 2) + c]);
                a[h][2] = tf32rn(sA[rb * 32 + (g1 << 2) + c]);
                a[h][3] = tf32rn(sA[(rb + 8) * 32 + (g1 << 2) + c]);
            }
#pragma unroll
            for (int nt = 0; nt < 4; nt++) {
                int rn = nt * 8 + r;
                uint32_t b0 = sB[rn * 32 + (g0 << 2) + c];
                uint32_t b1 = sB[rn * 32 + (g1 << 2) + c];
#pragma unroll
                for (int h = 0; h < 2; h++) {
                    asm volatile(
                        "mma.sync.aligned.m16n8k8.row.col.f32.tf32.tf32.f32 "
                        "{%0,%1,%2,%3}, {%4,%5,%6,%7}, {%8,%9}, {%0,%1,%2,%3};"
                        : "+f"(acc[h][nt][0]), "+f"(acc[h][nt][1]),
                          "+f"(acc[h][nt][2]), "+f"(acc[h][nt][3])
                        : "r"(a[h][0]), "r"(a[h][1]), "r"(a[h][2]), "r"(a[h][3]),
                          "r"(b0), "r"(b1));
                }
            }
        }
    };

    // ---- first item + pipeline priming (lead 2, 3 buffers) ----
    int cur = lo + blockIdx.x;            // host guarantees grid <= hi-lo
    const float *aB, *bB; int s, z, mt;
    decode(cur, aB, bB, s, z, mt);
    int bi = 0, bc = 0;                   // rotating issue/compute buffer ids
    issue(aB, bB, 0, bi); cp_commit(); bi = (bi + 1) % NSTAGES;
    issue(aB, bB, 1, bi); cp_commit(); bi = (bi + 1) % NSTAGES;

    while (true) {
        float acc[2][4][4];
#pragma unroll
        for (int h = 0; h < 2; h++)
#pragma unroll
            for (int nt = 0; nt < 4; nt++)
#pragma unroll
                for (int j = 0; j < 4; j++) acc[h][nt][j] = 0.0f;

        const float *naB = nullptr, *nbB = nullptr;
        int ns = 0, nz = 0, nmt = 0, nxt = hi;

#pragma unroll 1
        for (int st = 0; st < SPI; st++) {
            cp_wait1();                   // group st retired
            __syncthreads();              // visible to all; buffer bi free
            if (st == SPI - 3 && t == 0) s_next = atomicAdd(&g_ctr2[which], 1);
            if (st + 2 < SPI) {
                issue(aB, bB, st + 2, bi);
            } else {
                if (st == SPI - 2) {      // s_next write fenced by this barrier
                    nxt = s_next;
                    if (nxt < hi) decode(nxt, naB, nbB, ns, nz, nmt);
                }
                if (nxt < hi) issue(naB, nbB, st + 2 - SPI, bi);
            }
            cp_commit();                  // one group per iter, even if empty
            bi = (bi + 1) % NSTAGES;
            compute(bc, acc);
            bc = (bc + 1) % NSTAGES;
        }

        // ---- epilogue: deterministic partial store for item `cur` ----
        float* po = g_part[s * KSPLIT + z];
#pragma unroll
        for (int h = 0; h < 2; h++)
#pragma unroll
            for (int nt = 0; nt < 4; nt++)
#pragma unroll
                for (int q = 0; q < 2; q++) {
                    int m = mt * BM + m0w + h * 16 + r + 8 * q;
                    float2 v = make_float2(acc[h][nt][2 * q], acc[h][nt][2 * q + 1]);
                    *reinterpret_cast<float2*>(&po[(size_t)m * DD + nt * 8 + 2 * c]) = v;
                }

        if (nxt >= hi) break;
        cur = nxt; aB = naB; bB = nbB; s = ns; z = nz; mt = nmt;
    }
}

// ---------------------------------------------------------------------------
// Kernel 3: out = relu(sum over 24 partials)
// ---------------------------------------------------------------------------
__global__ __launch_bounds__(256) void reduce_kernel(float* __restrict__ out) {
    int i = blockIdx.x * 256 + threadIdx.x;
    float4 a = make_float4(0.f, 0.f, 0.f, 0.f);
#pragma unroll
    for (int p = 0; p < SS * KSPLIT; p++) {
        float4 v = reinterpret_cast<const float4*>(g_part[p])[i];
        a.x += v.x; a.y += v.y; a.z += v.z; a.w += v.w;
    }
    a.x = fmaxf(a.x, 0.f); a.y = fmaxf(a.y, 0.f);
    a.z = fmaxf(a.z, 0.f); a.w = fmaxf(a.w, 0.f);
    reinterpret_cast<float4*>(out)[i] = a;
}

// ---------------------------------------------------------------------------
// Launch: pre -> gemm half A -> gemm half B -> reduce   (4 launches)
// ---------------------------------------------------------------------------
extern "C" void kernel_launch(void* const* d_in, const int* in_sizes, int n_in,
                              void* d_out, int out_size) {
    const float* x   = (const float*)d_in[0];   // [8192, 32]
    const float* adj = (const float*)d_in[1];   // [3, 8192, 8192]
    const float* W   = (const float*)d_in[2];   // [3, 32, 32]
    const float* b   = (const float*)d_in[3];   // [3, 32]
    float* out = (float*)d_out;                 // [8192, 32]

    cudaFuncSetAttribute(gemm_kernel, cudaFuncAttributeMaxDynamicSharedMemorySize,
                         SMEM_FLOATS * 4);
    int sms = 148;
    cudaDeviceGetAttribute(&sms, cudaDevAttrMultiProcessorCount, 0);
    int workers = 2 * sms;
    if (workers > HALF_ITEMS) workers = HALF_ITEMS;

    pre_kernel<<<dim3(NN / 32, 4, SS), 256>>>(x, W, b, workers);
    gemm_kernel<<<workers, 256, SMEM_FLOATS * 4>>>(adj, 0, HALF_ITEMS, 0);
    gemm_kernel<<<workers, 256, SMEM_FLOATS * 4>>>(adj, HALF_ITEMS, NITEMS, 1);
    reduce_kernel<<<(NN * DD / 4) / 256, 256>>>(out);
}